// round 4
// baseline (speedup 1.0000x reference)
#include <cuda_runtime.h>
#include <cuda_bf16.h>
#include <cstdint>

#define Nn 50000
#define Ee 600000
#define Gg 512
#define Hh 128
#define SCAN_BLKS ((Nn + 255) / 256)   // 196

typedef unsigned long long u64;

// ---------------- device scratch (no allocations allowed) ----------------
__device__ __align__(16) float g_hw[(size_t)Nn * Hh];      // h @ W
__device__ __align__(16) float g_agg[(size_t)Nn * Hh];     // aggregated (also GEMM input)
__device__ __align__(16) float g_P[470 * Hh];              // projected embedding tables
__device__ __align__(16) float g_dinv[Nn];
__device__ __align__(16) float g_scale[Hh];
__device__ __align__(16) float g_shift[Hh];
__device__ __align__(16) float g_bnsum[3 * Hh];
__device__ __align__(16) float g_bnsq[3 * Hh];
__device__ __align__(16) float g_pooled[Gg * Hh];
__device__ __align__(16) float g_cnt[Gg];
__device__ int g_degcnt[Nn];
__device__ int g_cursor[Nn];
__device__ int g_base[Nn + 1];
__device__ int g_esrc[Ee];
__device__ int g_bsum[256];
__device__ int g_boff[256];

// ---------------- packed f32x2 helpers ----------------
__device__ __forceinline__ u64 pack2(float a) {
    u64 r; asm("mov.b64 %0, {%1, %1};" : "=l"(r) : "f"(a)); return r;
}
__device__ __forceinline__ void fma2(u64& acc, u64 a, u64 b) {
    asm("fma.rn.f32x2 %0, %1, %2, %0;" : "+l"(acc) : "l"(a), "l"(b));
}
__device__ __forceinline__ float2 unpack2(u64 v) {
    float2 f; asm("mov.b64 {%0, %1}, %2;" : "=f"(f.x), "=f"(f.y) : "l"(v)); return f;
}

// ---------------- init: zero accumulators ----------------
__global__ void k_init() {
    int i = blockIdx.x * blockDim.x + threadIdx.x;   // 65536 threads
    if (i < Nn) { g_degcnt[i] = 0; g_cursor[i] = 0; }
    if (i < Gg * Hh) g_pooled[i] = 0.0f;
    if (i < Gg) g_cnt[i] = 0.0f;
    if (i < 3 * Hh) { g_bnsum[i] = 0.0f; g_bnsq[i] = 0.0f; }
}

// ---------------- degree count + graph-size count ----------------
__global__ void k_count(const int* __restrict__ ei, const int* __restrict__ batch) {
    int j = blockIdx.x * blockDim.x + threadIdx.x;
    if (j < Ee) atomicAdd(&g_degcnt[ei[Ee + j]], 1);
    if (j < Nn) atomicAdd(&g_cnt[batch[j]], 1.0f);
}

__global__ void k_dinv() {
    int i = blockIdx.x * blockDim.x + threadIdx.x;
    if (i < Nn) g_dinv[i] = rsqrtf((float)g_degcnt[i] + 1.0f);
}

// ---------------- exclusive scan of degcnt -> g_base ----------------
__global__ void k_scan1() {
    __shared__ int sh[256];
    int tid = threadIdx.x;
    int i = blockIdx.x * 256 + tid;
    int v = (i < Nn) ? g_degcnt[i] : 0;
    sh[tid] = v; __syncthreads();
    for (int off = 1; off < 256; off <<= 1) {
        int y = (tid >= off) ? sh[tid - off] : 0;
        __syncthreads();
        sh[tid] += y;
        __syncthreads();
    }
    if (i < Nn) g_base[i] = sh[tid] - v;            // exclusive within block
    if (tid == 255) g_bsum[blockIdx.x] = sh[255];   // block total
}
__global__ void k_scan2() {
    __shared__ int sh[256];
    int tid = threadIdx.x;
    int v = (tid < SCAN_BLKS) ? g_bsum[tid] : 0;
    sh[tid] = v; __syncthreads();
    for (int off = 1; off < 256; off <<= 1) {
        int y = (tid >= off) ? sh[tid - off] : 0;
        __syncthreads();
        sh[tid] += y;
        __syncthreads();
    }
    g_boff[tid] = sh[tid] - v;                      // exclusive block offsets
}
__global__ void k_scan3() {
    int i = blockIdx.x * 256 + threadIdx.x;
    if (i < Nn) g_base[i] += g_boff[blockIdx.x];
    if (i == 0) g_base[Nn] = Ee;
}

// ---------------- place edges into CSR-by-dst ----------------
__global__ void k_place(const int* __restrict__ ei) {
    int e = blockIdx.x * blockDim.x + threadIdx.x;
    if (e >= Ee) return;
    int dst = ei[Ee + e];
    int pos = g_base[dst] + atomicAdd(&g_cursor[dst], 1);
    g_esrc[pos] = ei[e];
}

// ---------------- project one embedding table through W1 ----------------
__global__ void k_proj(const float* __restrict__ emb, const float* __restrict__ W1,
                       int koff, int poff) {
    int v = blockIdx.x, c = threadIdx.x;
    float acc = 0.0f;
#pragma unroll
    for (int j = 0; j < 32; j++)
        acc += emb[v * 32 + j] * W1[(koff + j) * Hh + c];
    g_P[(poff + v) * Hh + c] = acc;
}

// ---------------- layer-1 hw + agg init (embedding lookup form) ----------------
__global__ void k_layer1(const float* __restrict__ x, const float* __restrict__ W1,
                         const float* __restrict__ b1) {
    int i = blockIdx.x;
    int c = threadIdx.x;
    const float* xr = x + (size_t)i * 5;
    float pos = xr[0];
    int i0 = (int)xr[1], i1 = (int)xr[2], i2 = (int)xr[3], i5 = (int)xr[4];
    float v = pos * W1[c]
            + g_P[(size_t)i0 * Hh + c]
            + g_P[(size_t)(96 + i1) * Hh + c]
            + g_P[(size_t)(192 + i2) * Hh + c]
            + g_P[(size_t)(288 + i5) * Hh + c];
    g_hw[(size_t)i * Hh + c] = v;
    float d = g_dinv[i];
    g_agg[(size_t)i * Hh + c] = v * d * d + b1[c];
}

// ---------------- atomic-free aggregation: warp per node over CSR ----------------
__global__ void k_gather() {
    int gw = (blockIdx.x * blockDim.x + threadIdx.x) >> 5;
    if (gw >= Nn) return;
    int lane = threadIdx.x & 31;
    int s = g_base[gw], e = g_base[gw + 1];
    float di = g_dinv[gw];
    float4 acc = make_float4(0.f, 0.f, 0.f, 0.f);
    for (int t = s; t < e; t++) {
        int src = g_esrc[t];
        float nrm = g_dinv[src] * di;
        const float4 v = *(const float4*)(g_hw + (size_t)src * Hh + lane * 4);
        acc.x += v.x * nrm; acc.y += v.y * nrm;
        acc.z += v.z * nrm; acc.w += v.w * nrm;
    }
    float4* p = (float4*)(g_agg + (size_t)gw * Hh + lane * 4);
    float4 cur = *p;
    cur.x += acc.x; cur.y += acc.y; cur.z += acc.z; cur.w += acc.w;
    *p = cur;
}

// ---------------- BN statistics ----------------
__global__ void k_bnstats(int layer) {
    int c = threadIdx.x;
    int r0 = blockIdx.x * 128;
    int rend = min(r0 + 128, Nn);
    float s = 0.f, q = 0.f;
    for (int r = r0; r < rend; r++) {
        float v = g_agg[(size_t)r * Hh + c];
        s += v; q += v * v;
    }
    atomicAdd(&g_bnsum[layer * Hh + c], s);
    atomicAdd(&g_bnsq[layer * Hh + c], q);
}

__global__ void k_bnfin(int layer, const float* __restrict__ gamma,
                        const float* __restrict__ beta) {
    int c = threadIdx.x;
    float mean = g_bnsum[layer * Hh + c] * (1.0f / Nn);
    float var = g_bnsq[layer * Hh + c] * (1.0f / Nn) - mean * mean;
    float sc = gamma[c] * rsqrtf(var + 1e-5f);
    g_scale[c] = sc;
    g_shift[c] = beta[c] - mean * sc;
}

// ---------------- fused GEMM: relu(bn(A)) @ W, writes hw and agg init ----------------
// block tile 128 rows x 128 cols, 256 threads, 8x8 outputs/thread, f32x2 FMAs
#define GEMM_SMEM (128 * 132 * 4 + 128 * 128 * 4)
__global__ void __launch_bounds__(256, 1)
k_gemm(const float* __restrict__ W, const float* __restrict__ bias) {
    extern __shared__ float smem[];
    float* As = smem;                 // 128 x 132 (padded)
    float* Ws = smem + 128 * 132;     // 128 x 128
    int tid = threadIdx.x;
    int row0 = blockIdx.x * 128;

    // load W (16384 floats) as float4
    for (int t = tid; t < 128 * 128 / 4; t += 256)
        ((float4*)Ws)[t] = ((const float4*)W)[t];

    // load A tile with BN+ReLU transform, zero-pad OOB rows
    for (int t = tid; t < 128 * 32; t += 256) {
        int r = t >> 5, q = t & 31;
        int grow = row0 + r;
        float4 v = make_float4(0.f, 0.f, 0.f, 0.f);
        if (grow < Nn) {
            v = ((const float4*)(g_agg + (size_t)grow * Hh))[q];
            float4 sc = ((const float4*)g_scale)[q];
            float4 sh = ((const float4*)g_shift)[q];
            v.x = fmaxf(v.x * sc.x + sh.x, 0.f);
            v.y = fmaxf(v.y * sc.y + sh.y, 0.f);
            v.z = fmaxf(v.z * sc.z + sh.z, 0.f);
            v.w = fmaxf(v.w * sc.w + sh.w, 0.f);
        }
        *(float4*)(As + r * 132 + q * 4) = v;
    }
    __syncthreads();

    int tx = tid & 15;   // col group: cols tx*8 .. tx*8+7
    int ty = tid >> 4;   // row group: rows ty*8 .. ty*8+7

    u64 acc[8][4];
#pragma unroll
    for (int r = 0; r < 8; r++)
#pragma unroll
        for (int p = 0; p < 4; p++) acc[r][p] = 0ull;

    const float* As_r = As + ty * 8 * 132;
#pragma unroll 4
    for (int k = 0; k < 128; k++) {
        const u64* wk = (const u64*)(Ws + k * 128 + tx * 8);
        u64 w0 = wk[0], w1 = wk[1], w2 = wk[2], w3 = wk[3];
#pragma unroll
        for (int r = 0; r < 8; r++) {
            u64 a2 = pack2(As_r[r * 132 + k]);
            fma2(acc[r][0], a2, w0);
            fma2(acc[r][1], a2, w1);
            fma2(acc[r][2], a2, w2);
            fma2(acc[r][3], a2, w3);
        }
    }

    const float2* bp = (const float2*)(bias + tx * 8);
#pragma unroll
    for (int r = 0; r < 8; r++) {
        int grow = row0 + ty * 8 + r;
        if (grow >= Nn) continue;
        float di = g_dinv[grow];
        float d2 = di * di;
        float* hwp = g_hw + (size_t)grow * Hh + tx * 8;
        float* agp = g_agg + (size_t)grow * Hh + tx * 8;
#pragma unroll
        for (int p = 0; p < 4; p++) {
            float2 f = unpack2(acc[r][p]);
            float2 b2v = bp[p];
            *(float2*)(hwp + 2 * p) = f;
            float2 a2v;
            a2v.x = f.x * d2 + b2v.x;
            a2v.y = f.y * d2 + b2v.y;
            *(float2*)(agp + 2 * p) = a2v;
        }
    }
}

// ---------------- pooling: batch is sorted -> run-length accumulate ----------------
__global__ void k_pool(const int* __restrict__ batch) {
    __shared__ int sb[128];
    int c = threadIdx.x;
    int r0 = blockIdx.x * 128;
    int nrows = min(128, Nn - r0);
    if (c < nrows) sb[c] = batch[r0 + c];
    __syncthreads();
    float sc = g_scale[c], sh = g_shift[c];
    float acc = 0.f;
    int cur = sb[0];
    for (int r = 0; r < nrows; r++) {
        int gr = sb[r];
        if (gr != cur) { atomicAdd(&g_pooled[cur * Hh + c], acc); acc = 0.f; cur = gr; }
        float v = g_agg[(size_t)(r0 + r) * Hh + c];
        acc += fmaxf(v * sc + sh, 0.f);
    }
    atomicAdd(&g_pooled[cur * Hh + c], acc);
}

// ---------------- final FC: (pooled / cnt) @ fcW + fcb ----------------
__global__ void k_fc(const float* __restrict__ fcW, const float* __restrict__ fcb,
                     float* __restrict__ out) {
    int g = blockIdx.x, c = threadIdx.x;
    float v = g_pooled[g * Hh + c] / fmaxf(g_cnt[g], 1.0f);
    __shared__ float s0[128], s1[128], s2[128];
    s0[c] = v * fcW[c * 3 + 0];
    s1[c] = v * fcW[c * 3 + 1];
    s2[c] = v * fcW[c * 3 + 2];
    __syncthreads();
    for (int off = 64; off > 0; off >>= 1) {
        if (c < off) { s0[c] += s0[c + off]; s1[c] += s1[c + off]; s2[c] += s2[c + off]; }
        __syncthreads();
    }
    if (c == 0) {
        out[g * 3 + 0] = s0[0] + fcb[0];
        out[g * 3 + 1] = s1[0] + fcb[1];
        out[g * 3 + 2] = s2[0] + fcb[2];
    }
}

// ---------------- launch ----------------
extern "C" void kernel_launch(void* const* d_in, const int* in_sizes, int n_in,
                              void* d_out, int out_size) {
    const float* x     = (const float*)d_in[0];
    const int*   ei    = (const int*)  d_in[1];
    const int*   batch = (const int*)  d_in[2];
    const float* emb0  = (const float*)d_in[3];
    const float* emb1  = (const float*)d_in[4];
    const float* emb2  = (const float*)d_in[5];
    const float* emb5  = (const float*)d_in[6];
    const float* W1    = (const float*)d_in[7];
    const float* b1    = (const float*)d_in[8];
    const float* W2    = (const float*)d_in[9];
    const float* b2    = (const float*)d_in[10];
    const float* W3    = (const float*)d_in[11];
    const float* b3    = (const float*)d_in[12];
    const float* g1    = (const float*)d_in[13];
    const float* be1   = (const float*)d_in[14];
    const float* g2    = (const float*)d_in[15];
    const float* be2   = (const float*)d_in[16];
    const float* g3    = (const float*)d_in[17];
    const float* be3   = (const float*)d_in[18];
    const float* fcW   = (const float*)d_in[19];
    const float* fcb   = (const float*)d_in[20];
    float* out = (float*)d_out;

    cudaFuncSetAttribute(k_gemm, cudaFuncAttributeMaxDynamicSharedMemorySize, GEMM_SMEM);

    const int nblk = (Nn + 127) / 128;          // 391
    const int eblk = (Ee + 255) / 256;          // 2344
    const int gwb  = ((size_t)Nn * 32 + 255) / 256;  // warp-per-node blocks

    // graph preprocessing
    k_init<<<256, 256>>>();
    k_count<<<eblk, 256>>>(ei, batch);
    k_dinv<<<(Nn + 255) / 256, 256>>>();
    k_scan1<<<SCAN_BLKS, 256>>>();
    k_scan2<<<1, 256>>>();
    k_scan3<<<SCAN_BLKS, 256>>>();
    k_place<<<eblk, 256>>>(ei);

    // layer 1 (embedding-decomposed GEMM)
    k_proj<<<96, 128>>>(emb0, W1, 1, 0);
    k_proj<<<96, 128>>>(emb1, W1, 33, 96);
    k_proj<<<96, 128>>>(emb2, W1, 65, 192);
    k_proj<<<182, 128>>>(emb5, W1, 97, 288);
    k_layer1<<<Nn, 128>>>(x, W1, b1);
    k_gather<<<gwb, 256>>>();
    k_bnstats<<<nblk, 128>>>(0);
    k_bnfin<<<1, 128>>>(0, g1, be1);

    // layer 2
    k_gemm<<<nblk, 256, GEMM_SMEM>>>(W2, b2);
    k_gather<<<gwb, 256>>>();
    k_bnstats<<<nblk, 128>>>(1);
    k_bnfin<<<1, 128>>>(1, g2, be2);

    // layer 3
    k_gemm<<<nblk, 256, GEMM_SMEM>>>(W3, b3);
    k_gather<<<gwb, 256>>>();
    k_bnstats<<<nblk, 128>>>(2);
    k_bnfin<<<1, 128>>>(2, g3, be3);

    // pooling + classifier
    k_pool<<<nblk, 128>>>(batch);
    k_fc<<<Gg, 128>>>(fcW, fcb, out);
}